// round 2
// baseline (speedup 1.0000x reference)
#include <cuda_runtime.h>
#include <cstdint>

// Problem dims (fixed for this problem instance)
#define BB 2
#define TT 2048
#define DD 1024
#define HH 16
#define DHD 64
#define BT (BB*TT)      // 4096
#define DFF 4096
#define EPS 1e-6f

// ---------------------------------------------------------------------------
// Scratch (device globals; no allocation allowed)
// ---------------------------------------------------------------------------
__device__ float g_h   [(size_t)BT * DD];        // rmsnorm out (reused for h2)
__device__ float g_qkv [(size_t)BT * 3 * DD];    // qkv gemm out
__device__ float g_q   [(size_t)BT * DD];        // Q in [B,H,T,Dh]
__device__ float g_attn[(size_t)BT * DD];        // attention out [B,T,D]
__device__ float g_x1  [(size_t)BT * DD];        // post-attention residual
__device__ float g_gate[(size_t)BT * DFF];       // gate gemm out / swiglu act
__device__ float g_up  [(size_t)BT * DFF];       // up gemm out

// ---------------------------------------------------------------------------
// RMSNorm: one block per row, D=1024, 256 threads (1 float4/thread)
// ---------------------------------------------------------------------------
__global__ __launch_bounds__(256) void rmsnorm_k(const float* __restrict__ x,
                                                 const float* __restrict__ w,
                                                 float* __restrict__ o) {
    int row = blockIdx.x;
    int tid = threadIdx.x;
    const float4* xr = (const float4*)(x + (size_t)row * DD);
    float4 xv = xr[tid];
    float ss = xv.x * xv.x + xv.y * xv.y + xv.z * xv.z + xv.w * xv.w;
    #pragma unroll
    for (int off = 16; off; off >>= 1) ss += __shfl_xor_sync(0xffffffffu, ss, off);
    __shared__ float sred[8];
    if ((tid & 31) == 0) sred[tid >> 5] = ss;
    __syncthreads();
    if (tid < 8) {
        float v = sred[tid];
        #pragma unroll
        for (int off = 4; off; off >>= 1) v += __shfl_xor_sync(0xffu, v, off);
        if (tid == 0) sred[0] = v;
    }
    __syncthreads();
    float inv = rsqrtf(sred[0] * (1.0f / DD) + EPS);
    float4 wv = ((const float4*)w)[tid];
    float4 ov = make_float4(xv.x * inv * wv.x, xv.y * inv * wv.y,
                            xv.z * inv * wv.z, xv.w * inv * wv.w);
    ((float4*)(o + (size_t)row * DD))[tid] = ov;
}

// ---------------------------------------------------------------------------
// SGEMM NT: C[M,N] = A[M,K] * B[N,K]^T (+ optional residual R[M,N])
// 128x128 tile, BK=8, 256 threads, 8x8 per thread, double-buffered smem.
// M,N multiples of 128; K multiple of 8.
// ---------------------------------------------------------------------------
__global__ __launch_bounds__(256) void sgemm_nt(const float* __restrict__ A,
                                                const float* __restrict__ B,
                                                const float* __restrict__ R,
                                                float* __restrict__ C,
                                                int M, int N, int K) {
    __shared__ float As[2][8][128];
    __shared__ float Bs[2][8][128];
    int tid = threadIdx.x;
    int bm = blockIdx.y, bn = blockIdx.x;
    int tx = tid & 15, ty = tid >> 4;

    int lrow = tid >> 1;           // 0..127
    int lcol = (tid & 1) * 4;      // 0 or 4
    const float* Ag = A + (size_t)(bm * 128 + lrow) * K + lcol;
    const float* Bg = B + (size_t)(bn * 128 + lrow) * K + lcol;

    float acc[8][8];
    #pragma unroll
    for (int i = 0; i < 8; i++)
        #pragma unroll
        for (int j = 0; j < 8; j++) acc[i][j] = 0.0f;

    // prologue: stage 0
    {
        float4 av = *(const float4*)Ag;
        float4 bv = *(const float4*)Bg;
        As[0][lcol + 0][lrow] = av.x; As[0][lcol + 1][lrow] = av.y;
        As[0][lcol + 2][lrow] = av.z; As[0][lcol + 3][lrow] = av.w;
        Bs[0][lcol + 0][lrow] = bv.x; Bs[0][lcol + 1][lrow] = bv.y;
        Bs[0][lcol + 2][lrow] = bv.z; Bs[0][lcol + 3][lrow] = bv.w;
    }
    __syncthreads();

    int buf = 0;
    for (int k0 = 8; k0 < K + 8; k0 += 8) {
        bool more = (k0 < K);
        float4 an, bn4;
        if (more) {
            an  = *(const float4*)(Ag + k0);
            bn4 = *(const float4*)(Bg + k0);
        }
        #pragma unroll
        for (int k = 0; k < 8; k++) {
            float a[8], b[8];
            *(float4*)(a + 0) = *(const float4*)&As[buf][k][ty * 4];
            *(float4*)(a + 4) = *(const float4*)&As[buf][k][64 + ty * 4];
            *(float4*)(b + 0) = *(const float4*)&Bs[buf][k][tx * 4];
            *(float4*)(b + 4) = *(const float4*)&Bs[buf][k][64 + tx * 4];
            #pragma unroll
            for (int i = 0; i < 8; i++)
                #pragma unroll
                for (int j = 0; j < 8; j++) acc[i][j] += a[i] * b[j];
        }
        if (more) {
            int nb = buf ^ 1;
            As[nb][lcol + 0][lrow] = an.x;  As[nb][lcol + 1][lrow] = an.y;
            As[nb][lcol + 2][lrow] = an.z;  As[nb][lcol + 3][lrow] = an.w;
            Bs[nb][lcol + 0][lrow] = bn4.x; Bs[nb][lcol + 1][lrow] = bn4.y;
            Bs[nb][lcol + 2][lrow] = bn4.z; Bs[nb][lcol + 3][lrow] = bn4.w;
            __syncthreads();
            buf = nb;
        }
    }

    int rbase = bm * 128, cbase = bn * 128;
    #pragma unroll
    for (int i = 0; i < 8; i++) {
        int rl = (i < 4) ? (ty * 4 + i) : (64 + ty * 4 + i - 4);
        size_t roff = (size_t)(rbase + rl) * N + cbase;
        float* Cr = C + roff;
        float4 v0 = make_float4(acc[i][0], acc[i][1], acc[i][2], acc[i][3]);
        float4 v1 = make_float4(acc[i][4], acc[i][5], acc[i][6], acc[i][7]);
        if (R) {
            const float* Rr = R + roff;
            float4 r0 = *(const float4*)&Rr[tx * 4];
            float4 r1 = *(const float4*)&Rr[64 + tx * 4];
            v0.x += r0.x; v0.y += r0.y; v0.z += r0.z; v0.w += r0.w;
            v1.x += r1.x; v1.y += r1.y; v1.z += r1.z; v1.w += r1.w;
        }
        *(float4*)&Cr[tx * 4]      = v0;
        *(float4*)&Cr[64 + tx * 4] = v1;
    }
}

// ---------------------------------------------------------------------------
// Scatter QKV gemm output [BT, 3D] into Q scratch [B,H,T,Dh] and K/V caches
// (the caches live in d_out; T == CTX so they are fully written).
// ---------------------------------------------------------------------------
__global__ __launch_bounds__(256) void qkv_scatter(const float4* __restrict__ qkv,
                                                   float* __restrict__ q,
                                                   float* __restrict__ kc,
                                                   float* __restrict__ vc) {
    size_t e = (size_t)blockIdx.x * 256 + threadIdx.x;
    const size_t total = (size_t)BT * 3 * DD / 4;
    if (e >= total) return;
    int m  = (int)(e / 768);        // row: 3*D/4 = 768 float4 per row
    int nn = (int)(e % 768) * 4;    // column (element)
    int which = nn >> 10;           // 0=q 1=k 2=v
    int head  = (nn >> 6) & 15;
    int dh    = nn & 63;
    int b = m >> 11;                // / 2048
    int t = m & 2047;
    float4 val = qkv[e];
    size_t dst = (((size_t)(b * HH + head)) * TT + t) * DHD + dh;
    float* p = (which == 0) ? q : (which == 1) ? kc : vc;
    *(float4*)(p + dst) = val;
}

// ---------------------------------------------------------------------------
// Flash attention (prefill, causal). One block per (b*h, q-tile of 64 rows).
// KV tiles of 32 keys. Streaming softmax. Dh = 64.
// Shared: qs[64][65], ks[max(32*65, 64*33)] (K tile, then reused for P), vs[32][64]
// Total: (4160 + 2112 + 2048) * 4 = 33,280 B (static, under 48KB)
// ---------------------------------------------------------------------------
__global__ __launch_bounds__(256) void attn_k(const float* __restrict__ Q,
                                              const float* __restrict__ Kc,
                                              const float* __restrict__ Vc,
                                              float* __restrict__ Out) {
    __shared__ float qs[64 * 65];
    __shared__ float ks[2112];      // K tile [32][65] (2080) or P [64][33] (2112)
    __shared__ float vs[32 * 64];

    int qt = blockIdx.x;            // q tile 0..31
    int bh = blockIdx.y;            // 0..31
    int tid = threadIdx.x;
    int tx = tid & 15, ty = tid >> 4;

    const float* qb = Q + ((size_t)bh * TT + qt * 64) * DHD;
    // load Q tile 64x64 (1024 float4, 4 per thread), smem stride 65
    #pragma unroll
    for (int it = 0; it < 4; it++) {
        int e = it * 256 + tid;
        int r = e >> 4, c4 = (e & 15) * 4;
        float4 v = *(const float4*)(qb + r * 64 + c4);
        qs[r * 65 + c4 + 0] = v.x; qs[r * 65 + c4 + 1] = v.y;
        qs[r * 65 + c4 + 2] = v.z; qs[r * 65 + c4 + 3] = v.w;
    }

    float m[4], l[4], o[4][4];
    #pragma unroll
    for (int i = 0; i < 4; i++) {
        m[i] = -1e30f; l[i] = 0.0f;
        #pragma unroll
        for (int j = 0; j < 4; j++) o[i][j] = 0.0f;
    }
    const float scale = 0.125f;     // 1/sqrt(64)
    int ntiles = 2 * qt + 2;        // keys up to (qt+1)*64

    for (int j = 0; j < ntiles; j++) {
        __syncthreads();  // prev iter's PV reads done (also spaces qs store)
        const float* kb = Kc + ((size_t)bh * TT + j * 32) * DHD;
        const float* vb = Vc + ((size_t)bh * TT + j * 32) * DHD;
        #pragma unroll
        for (int it = 0; it < 2; it++) {
            int e = it * 256 + tid;
            int r = e >> 4, c4 = (e & 15) * 4;
            float4 kv4 = *(const float4*)(kb + r * 64 + c4);
            ks[r * 65 + c4 + 0] = kv4.x; ks[r * 65 + c4 + 1] = kv4.y;
            ks[r * 65 + c4 + 2] = kv4.z; ks[r * 65 + c4 + 3] = kv4.w;
            float4 vv4 = *(const float4*)(vb + r * 64 + c4);
            *(float4*)&vs[r * 64 + c4] = vv4;
        }
        __syncthreads();

        // S[64x32]: rows r = 4*ty+i, cols c = 2*tx+jj
        float s[4][2];
        #pragma unroll
        for (int i = 0; i < 4; i++) { s[i][0] = 0.0f; s[i][1] = 0.0f; }
        #pragma unroll 16
        for (int k = 0; k < 64; k++) {
            float qv[4], kv[2];
            #pragma unroll
            for (int i = 0; i < 4; i++) qv[i] = qs[(4 * ty + i) * 65 + k];
            kv[0] = ks[(2 * tx + 0) * 65 + k];
            kv[1] = ks[(2 * tx + 1) * 65 + k];
            #pragma unroll
            for (int i = 0; i < 4; i++) {
                s[i][0] += qv[i] * kv[0];
                s[i][1] += qv[i] * kv[1];
            }
        }
        // scale + causal mask (only tiles intersecting the diagonal)
        bool need_mask = (j >= 2 * qt);
        #pragma unroll
        for (int i = 0; i < 4; i++) {
            int qrow = qt * 64 + 4 * ty + i;
            #pragma unroll
            for (int jj = 0; jj < 2; jj++) {
                s[i][jj] *= scale;
                int key = j * 32 + 2 * tx + jj;
                if (need_mask && key > qrow) s[i][jj] = -1e30f;
            }
        }
        // streaming softmax per row (reduce over 16-lane tx group)
        #pragma unroll
        for (int i = 0; i < 4; i++) {
            float rm = fmaxf(s[i][0], s[i][1]);
            #pragma unroll
            for (int off = 1; off < 16; off <<= 1)
                rm = fmaxf(rm, __shfl_xor_sync(0xffffffffu, rm, off));
            float nm = fmaxf(m[i], rm);
            float corr = __expf(m[i] - nm);
            float p0 = __expf(s[i][0] - nm);
            float p1 = __expf(s[i][1] - nm);
            float rs = p0 + p1;
            #pragma unroll
            for (int off = 1; off < 16; off <<= 1)
                rs += __shfl_xor_sync(0xffffffffu, rs, off);
            l[i] = l[i] * corr + rs;
            m[i] = nm;
            s[i][0] = p0; s[i][1] = p1;
            #pragma unroll
            for (int jj = 0; jj < 4; jj++) o[i][jj] *= corr;
        }
        __syncthreads();  // everyone done reading ks as K
        // store P [64 rows][32 keys] into ks with stride 33
        #pragma unroll
        for (int i = 0; i < 4; i++) {
            ks[(4 * ty + i) * 33 + 2 * tx + 0] = s[i][0];
            ks[(4 * ty + i) * 33 + 2 * tx + 1] = s[i][1];
        }
        __syncthreads();
        // O[64x64] += P[64x32] @ V[32x64]; O cols c = 4*tx+j4
        #pragma unroll 8
        for (int k = 0; k < 32; k++) {
            float pv[4];
            #pragma unroll
            for (int i = 0; i < 4; i++) pv[i] = ks[(4 * ty + i) * 33 + k];
            float4 vv = *(const float4*)&vs[k * 64 + tx * 4];
            #pragma unroll
            for (int i = 0; i < 4; i++) {
                o[i][0] += pv[i] * vv.x;
                o[i][1] += pv[i] * vv.y;
                o[i][2] += pv[i] * vv.z;
                o[i][3] += pv[i] * vv.w;
            }
        }
    }

    // epilogue: Out[b, t, head*64+dh]
    int b = bh >> 4, head = bh & 15;
    #pragma unroll
    for (int i = 0; i < 4; i++) {
        float invl = 1.0f / l[i];
        int t = qt * 64 + 4 * ty + i;
        float* dst = Out + ((size_t)b * TT + t) * DD + head * 64 + tx * 4;
        *(float4*)dst = make_float4(o[i][0] * invl, o[i][1] * invl,
                                    o[i][2] * invl, o[i][3] * invl);
    }
}

// ---------------------------------------------------------------------------
// SwiGLU elementwise
// ---------------------------------------------------------------------------
__global__ __launch_bounds__(256) void swiglu_k(const float4* __restrict__ g,
                                                const float4* __restrict__ u,
                                                float4* __restrict__ o, size_t n4) {
    size_t i = (size_t)blockIdx.x * 256 + threadIdx.x;
    if (i >= n4) return;
    float4 gv = g[i], uv = u[i];
    float4 r;
    r.x = gv.x / (1.0f + __expf(-gv.x)) * uv.x;
    r.y = gv.y / (1.0f + __expf(-gv.y)) * uv.y;
    r.z = gv.z / (1.0f + __expf(-gv.z)) * uv.z;
    r.w = gv.w / (1.0f + __expf(-gv.w)) * uv.w;
    o[i] = r;
}

// ---------------------------------------------------------------------------
// Launch
// ---------------------------------------------------------------------------
extern "C" void kernel_launch(void* const* d_in, const int* in_sizes, int n_in,
                              void* d_out, int out_size) {
    const float* x     = (const float*)d_in[0];
    const float* w1    = (const float*)d_in[1];
    const float* wqkv  = (const float*)d_in[2];
    const float* wproj = (const float*)d_in[3];
    const float* w2    = (const float*)d_in[4];
    const float* wgate = (const float*)d_in[5];
    const float* wup   = (const float*)d_in[6];
    const float* wdown = (const float*)d_in[7];

    float* out   = (float*)d_out;
    float* out_x = out;
    float* out_k = out + (size_t)BT * DD;
    float* out_v = out + 2 * (size_t)BT * DD;

    float *h, *qkv, *q, *attn, *x1, *gate, *up;
    cudaGetSymbolAddress((void**)&h,    g_h);
    cudaGetSymbolAddress((void**)&qkv,  g_qkv);
    cudaGetSymbolAddress((void**)&q,    g_q);
    cudaGetSymbolAddress((void**)&attn, g_attn);
    cudaGetSymbolAddress((void**)&x1,   g_x1);
    cudaGetSymbolAddress((void**)&gate, g_gate);
    cudaGetSymbolAddress((void**)&up,   g_up);

    const size_t n4_ff  = (size_t)BT * DFF / 4;    // 4,194,304
    const size_t n4_qkv = (size_t)BT * 3 * DD / 4; // 3,145,728

    // 1) h = rmsnorm(x, w1)
    rmsnorm_k<<<BT, 256>>>(x, w1, h);
    // 2) qkv = h @ w_qkv^T
    sgemm_nt<<<dim3(3 * DD / 128, BT / 128), 256>>>(h, wqkv, nullptr, qkv, BT, 3 * DD, DD);
    // 3) scatter into q scratch + k/v caches (in d_out)
    qkv_scatter<<<(unsigned)((n4_qkv + 255) / 256), 256>>>((const float4*)qkv, q, out_k, out_v);
    // 4) attention
    attn_k<<<dim3(TT / 64, BB * HH), 256>>>(q, out_k, out_v, attn);
    // 5) x1 = x + attn @ w_proj^T   (residual fused)
    sgemm_nt<<<dim3(DD / 128, BT / 128), 256>>>(attn, wproj, x, x1, BT, DD, DD);
    // 6) h2 = rmsnorm(x1, w2)   (reuse h)
    rmsnorm_k<<<BT, 256>>>(x1, w2, h);
    // 7) gate = h2 @ w_gate^T ; up = h2 @ w_up^T
    sgemm_nt<<<dim3(DFF / 128, BT / 128), 256>>>(h, wgate, nullptr, gate, BT, DFF, DD);
    sgemm_nt<<<dim3(DFF / 128, BT / 128), 256>>>(h, wup, nullptr, up, BT, DFF, DD);
    // 8) act = silu(gate) * up  (into gate)
    swiglu_k<<<(unsigned)((n4_ff + 255) / 256), 256>>>((const float4*)gate, (const float4*)up, (float4*)gate, n4_ff);
    // 9) out_x = x1 + act @ w_down^T   (residual fused)
    sgemm_nt<<<dim3(DD / 128, BT / 128), 256>>>(gate, wdown, x1, out_x, BT, DD, DFF);
}

// round 3
// speedup vs baseline: 1.2387x; 1.2387x over previous
#include <cuda_runtime.h>
#include <cstdint>

#define BB 2
#define TT 2048
#define DD 1024
#define HH 16
#define DHD 64
#define BT (BB*TT)      // 4096
#define DFF 4096
#define EPS 1e-6f

// ---------------------------------------------------------------------------
// Scratch (device globals; no allocation allowed)
// ---------------------------------------------------------------------------
__device__ float g_h   [(size_t)BT * DD];        // rmsnorm out (reused for h2)
__device__ float g_q   [(size_t)BT * DD];        // Q in [B,H,T,Dh]
__device__ float g_attn[(size_t)BT * DD];        // attention out [B,T,D]
__device__ float g_x1  [(size_t)BT * DD];        // post-attention residual
__device__ float g_gate[(size_t)BT * DFF];       // gate gemm out / swiglu act
__device__ float g_up  [(size_t)BT * DFF];       // up gemm out

// ---------------------------------------------------------------------------
// Helpers
// ---------------------------------------------------------------------------
__device__ __forceinline__ float f2tf32(float f) {
    uint32_t u;
    asm("cvt.rna.tf32.f32 %0, %1;" : "=r"(u) : "f"(f));
    return __uint_as_float(u);
}

__device__ __forceinline__ void mma_tf32(float* c, const uint32_t* a, const uint32_t* b) {
    asm volatile(
        "mma.sync.aligned.m16n8k8.row.col.f32.tf32.tf32.f32 "
        "{%0,%1,%2,%3}, {%4,%5,%6,%7}, {%8,%9}, {%0,%1,%2,%3};\n"
        : "+f"(c[0]), "+f"(c[1]), "+f"(c[2]), "+f"(c[3])
        : "r"(a[0]), "r"(a[1]), "r"(a[2]), "r"(a[3]), "r"(b[0]), "r"(b[1]));
}

// ---------------------------------------------------------------------------
// RMSNorm: one block per row, D=1024, 256 threads (1 float4/thread)
// ---------------------------------------------------------------------------
__global__ __launch_bounds__(256) void rmsnorm_k(const float* __restrict__ x,
                                                 const float* __restrict__ w,
                                                 float* __restrict__ o) {
    int row = blockIdx.x;
    int tid = threadIdx.x;
    const float4* xr = (const float4*)(x + (size_t)row * DD);
    float4 xv = xr[tid];
    float ss = xv.x * xv.x + xv.y * xv.y + xv.z * xv.z + xv.w * xv.w;
    #pragma unroll
    for (int off = 16; off; off >>= 1) ss += __shfl_xor_sync(0xffffffffu, ss, off);
    __shared__ float sred[8];
    if ((tid & 31) == 0) sred[tid >> 5] = ss;
    __syncthreads();
    if (tid < 8) {
        float v = sred[tid];
        #pragma unroll
        for (int off = 4; off; off >>= 1) v += __shfl_xor_sync(0xffu, v, off);
        if (tid == 0) sred[0] = v;
    }
    __syncthreads();
    float inv = rsqrtf(sred[0] * (1.0f / DD) + EPS);
    float4 wv = ((const float4*)w)[tid];
    float4 ov = make_float4(xv.x * inv * wv.x, xv.y * inv * wv.y,
                            xv.z * inv * wv.z, xv.w * inv * wv.w);
    ((float4*)(o + (size_t)row * DD))[tid] = ov;
}

// ---------------------------------------------------------------------------
// TF32 tensor-core GEMM NT: C[M,N] = A[M,K] * B[N,K]^T (+ optional R)
// 128x128 block tile, BK=8, double-buffered, 8 warps (warp tile 64x32).
// mode 0: plain output (C, optional residual R)
// mode 1: QKV scatter epilogue -> qp (Q [B,H,T,Dh]) / kp / vp (caches)
// ---------------------------------------------------------------------------
__global__ __launch_bounds__(256) void gemm_tf32(
    const float* __restrict__ A, const float* __restrict__ B,
    const float* __restrict__ R, float* __restrict__ C,
    int M, int N, int K, int mode,
    float* __restrict__ qp, float* __restrict__ kp, float* __restrict__ vp)
{
    __shared__ float As[2][8][136];   // stride 136 ≡ 8 (mod 32): conflict-free
    __shared__ float Bs[2][8][136];

    int tid  = threadIdx.x;
    int bm   = blockIdx.y, bn = blockIdx.x;
    int lane = tid & 31, wid = tid >> 5;
    int wm   = (wid & 1) * 64;
    int wn   = (wid >> 1) * 32;
    int gid  = lane >> 2, tig = lane & 3;

    int ar = tid & 127;          // row within tile
    int ac = (tid >> 7) * 4;     // k sub-offset 0 or 4
    const float* Ag = A + (size_t)(bm * 128 + ar) * K + ac;
    const float* Bg = B + (size_t)(bn * 128 + ar) * K + ac;

    float acc[4][4][4];
    #pragma unroll
    for (int mi = 0; mi < 4; mi++)
        #pragma unroll
        for (int ni = 0; ni < 4; ni++)
            #pragma unroll
            for (int e = 0; e < 4; e++) acc[mi][ni][e] = 0.0f;

    // prologue: stage 0
    {
        float4 av = *(const float4*)Ag;
        float4 bv = *(const float4*)Bg;
        As[0][ac + 0][ar] = f2tf32(av.x); As[0][ac + 1][ar] = f2tf32(av.y);
        As[0][ac + 2][ar] = f2tf32(av.z); As[0][ac + 3][ar] = f2tf32(av.w);
        Bs[0][ac + 0][ar] = f2tf32(bv.x); Bs[0][ac + 1][ar] = f2tf32(bv.y);
        Bs[0][ac + 2][ar] = f2tf32(bv.z); Bs[0][ac + 3][ar] = f2tf32(bv.w);
    }
    __syncthreads();

    int buf = 0;
    for (int k0 = 8; k0 < K + 8; k0 += 8) {
        bool more = (k0 < K);
        float4 av, bv;
        if (more) {
            av = *(const float4*)(Ag + k0);
            bv = *(const float4*)(Bg + k0);
        }

        uint32_t afr[4][4], bfr[4][2];
        #pragma unroll
        for (int mi = 0; mi < 4; mi++) {
            int m0 = wm + mi * 16 + gid;
            afr[mi][0] = __float_as_uint(As[buf][tig    ][m0    ]);
            afr[mi][1] = __float_as_uint(As[buf][tig    ][m0 + 8]);
            afr[mi][2] = __float_as_uint(As[buf][tig + 4][m0    ]);
            afr[mi][3] = __float_as_uint(As[buf][tig + 4][m0 + 8]);
        }
        #pragma unroll
        for (int ni = 0; ni < 4; ni++) {
            int n0 = wn + ni * 8 + gid;
            bfr[ni][0] = __float_as_uint(Bs[buf][tig    ][n0]);
            bfr[ni][1] = __float_as_uint(Bs[buf][tig + 4][n0]);
        }
        #pragma unroll
        for (int mi = 0; mi < 4; mi++)
            #pragma unroll
            for (int ni = 0; ni < 4; ni++)
                mma_tf32(acc[mi][ni], afr[mi], bfr[ni]);

        if (more) {
            int nb = buf ^ 1;
            As[nb][ac + 0][ar] = f2tf32(av.x); As[nb][ac + 1][ar] = f2tf32(av.y);
            As[nb][ac + 2][ar] = f2tf32(av.z); As[nb][ac + 3][ar] = f2tf32(av.w);
            Bs[nb][ac + 0][ar] = f2tf32(bv.x); Bs[nb][ac + 1][ar] = f2tf32(bv.y);
            Bs[nb][ac + 2][ar] = f2tf32(bv.z); Bs[nb][ac + 3][ar] = f2tf32(bv.w);
            __syncthreads();
            buf = nb;
        }
    }

    // epilogue
    #pragma unroll
    for (int mi = 0; mi < 4; mi++) {
        #pragma unroll
        for (int ni = 0; ni < 4; ni++) {
            int r0 = bm * 128 + wm + mi * 16 + gid;
            int c0 = bn * 128 + wn + ni * 8 + 2 * tig;
            float2 v0 = make_float2(acc[mi][ni][0], acc[mi][ni][1]);
            float2 v1 = make_float2(acc[mi][ni][2], acc[mi][ni][3]);
            if (mode == 0) {
                size_t off0 = (size_t)r0 * N + c0;
                size_t off1 = off0 + (size_t)8 * N;
                if (R) {
                    float2 a0 = *(const float2*)(R + off0);
                    float2 a1 = *(const float2*)(R + off1);
                    v0.x += a0.x; v0.y += a0.y;
                    v1.x += a1.x; v1.y += a1.y;
                }
                *(float2*)(C + off0) = v0;
                *(float2*)(C + off1) = v1;
            } else {
                // scatter: (m, nn) -> which/head/dh, [B,H,T,Dh]
                #pragma unroll
                for (int half = 0; half < 2; half++) {
                    int m = r0 + half * 8;
                    int b = m >> 11, t = m & 2047;
                    int which = c0 >> 10;
                    int head  = (c0 >> 6) & 15;
                    int dh    = c0 & 63;
                    float* p = (which == 0) ? qp : (which == 1) ? kp : vp;
                    size_t dst = (((size_t)(b * HH + head)) * TT + t) * DHD + dh;
                    *(float2*)(p + dst) = half ? v1 : v0;
                }
            }
        }
    }
}

// ---------------------------------------------------------------------------
// Flash attention (prefill, causal). Block = (q-tile 64 rows, one b*h).
// KV tile 64. Thread: 4x4 S/O. Exactly 48KB static smem.
// K and P stored rotation-swizzled: idx = (k + c + (c>>1)) & 63 -> the 16
// column addresses per warp land in 16 distinct banks.
// ---------------------------------------------------------------------------
__global__ __launch_bounds__(256) void attn_k(const float* __restrict__ Q,
                                              const float* __restrict__ Kc,
                                              const float* __restrict__ Vc,
                                              float* __restrict__ Out) {
    __shared__ float qs[64 * 64];   // scaled Q, row-major
    __shared__ float ks[64 * 64];   // K (rot-swizzled), reused for P
    __shared__ float vs[64 * 64];   // V, row-major

    int qt = blockIdx.x;
    int bh = blockIdx.y;
    int tid = threadIdx.x;
    int tx = tid & 15, ty = tid >> 4;
    int c0 = 4 * tx;
    int r0 = 4 * ty;

    const float* qb = Q + ((size_t)bh * TT + qt * 64) * DHD;
    #pragma unroll
    for (int it = 0; it < 4; it++) {
        int e = it * 256 + tid;
        int r = e >> 4, c4 = (e & 15) * 4;
        float4 v = *(const float4*)(qb + r * 64 + c4);
        v.x *= 0.125f; v.y *= 0.125f; v.z *= 0.125f; v.w *= 0.125f;
        *(float4*)&qs[r * 64 + c4] = v;
    }

    float m[4], l[4], o[4][4];
    #pragma unroll
    for (int i = 0; i < 4; i++) {
        m[i] = -1e30f; l[i] = 0.0f;
        #pragma unroll
        for (int jj = 0; jj < 4; jj++) o[i][jj] = 0.0f;
    }

    int ntiles = qt + 1;
    for (int j = 0; j < ntiles; j++) {
        __syncthreads();   // prev PV reads of ks/vs done; qs stores done (j==0)
        const float* kb = Kc + ((size_t)bh * TT + j * 64) * DHD;
        const float* vb = Vc + ((size_t)bh * TT + j * 64) * DHD;
        #pragma unroll
        for (int it = 0; it < 4; it++) {
            int e = it * 256 + tid;
            int r = e >> 4, c4 = (e & 15) * 4;
            int g = r + (r >> 1);          // swizzle offset for key-row r
            float4 kv = *(const float4*)(kb + r * 64 + c4);
            ks[r * 64 + ((c4 + 0 + g) & 63)] = kv.x;
            ks[r * 64 + ((c4 + 1 + g) & 63)] = kv.y;
            ks[r * 64 + ((c4 + 2 + g) & 63)] = kv.z;
            ks[r * 64 + ((c4 + 3 + g) & 63)] = kv.w;
            float4 vv = *(const float4*)(vb + r * 64 + c4);
            *(float4*)&vs[r * 64 + c4] = vv;
        }
        __syncthreads();

        // S[64x64]: rows r0+i, cols c0+jj
        float s[4][4];
        #pragma unroll
        for (int i = 0; i < 4; i++)
            #pragma unroll
            for (int jj = 0; jj < 4; jj++) s[i][jj] = 0.0f;

        int gc[4];
        #pragma unroll
        for (int jj = 0; jj < 4; jj++) {
            int c = c0 + jj;
            gc[jj] = c + (c >> 1);
        }
        #pragma unroll 8
        for (int k = 0; k < 64; k++) {
            float qv[4], kv[4];
            #pragma unroll
            for (int i = 0; i < 4; i++) qv[i] = qs[(r0 + i) * 64 + k];
            #pragma unroll
            for (int jj = 0; jj < 4; jj++)
                kv[jj] = ks[(c0 + jj) * 64 + ((k + gc[jj]) & 63)];
            #pragma unroll
            for (int i = 0; i < 4; i++)
                #pragma unroll
                for (int jj = 0; jj < 4; jj++)
                    s[i][jj] += qv[i] * kv[jj];
        }

        // causal mask (only the diagonal tile)
        if (j == qt) {
            #pragma unroll
            for (int i = 0; i < 4; i++) {
                int qrow = qt * 64 + r0 + i;
                #pragma unroll
                for (int jj = 0; jj < 4; jj++) {
                    int key = j * 64 + c0 + jj;
                    if (key > qrow) s[i][jj] = -1e30f;
                }
            }
        }

        // streaming softmax (reduce over 16 tx lanes)
        #pragma unroll
        for (int i = 0; i < 4; i++) {
            float rm = fmaxf(fmaxf(s[i][0], s[i][1]), fmaxf(s[i][2], s[i][3]));
            #pragma unroll
            for (int off = 1; off < 16; off <<= 1)
                rm = fmaxf(rm, __shfl_xor_sync(0xffffffffu, rm, off));
            float nm = fmaxf(m[i], rm);
            float corr = __expf(m[i] - nm);
            float rs = 0.0f;
            #pragma unroll
            for (int jj = 0; jj < 4; jj++) {
                s[i][jj] = __expf(s[i][jj] - nm);
                rs += s[i][jj];
            }
            #pragma unroll
            for (int off = 1; off < 16; off <<= 1)
                rs += __shfl_xor_sync(0xffffffffu, rs, off);
            l[i] = l[i] * corr + rs;
            m[i] = nm;
            #pragma unroll
            for (int jj = 0; jj < 4; jj++) o[i][jj] *= corr;
        }

        __syncthreads();   // everyone done reading ks as K
        // store P rotated into ks: P[r][c] at ks[r*64 + ((c + r + (r>>1)) & 63)]
        #pragma unroll
        for (int i = 0; i < 4; i++) {
            int r = r0 + i;
            int g = r + (r >> 1);
            #pragma unroll
            for (int jj = 0; jj < 4; jj++)
                ks[r * 64 + ((c0 + jj + g) & 63)] = s[i][jj];
        }
        __syncthreads();

        // O[64x64] += P[64x64] @ V[64x64]
        int gr[4];
        #pragma unroll
        for (int i = 0; i < 4; i++) {
            int r = r0 + i;
            gr[i] = r + (r >> 1);
        }
        #pragma unroll 8
        for (int k = 0; k < 64; k++) {
            float pv[4];
            #pragma unroll
            for (int i = 0; i < 4; i++)
                pv[i] = ks[(r0 + i) * 64 + ((k + gr[i]) & 63)];
            float4 vv = *(const float4*)&vs[k * 64 + c0];
            #pragma unroll
            for (int i = 0; i < 4; i++) {
                o[i][0] += pv[i] * vv.x;
                o[i][1] += pv[i] * vv.y;
                o[i][2] += pv[i] * vv.z;
                o[i][3] += pv[i] * vv.w;
            }
        }
    }

    // epilogue: Out[b, t, head*64 + c0..c0+3]
    int b = bh >> 4, head = bh & 15;
    #pragma unroll
    for (int i = 0; i < 4; i++) {
        float invl = 1.0f / l[i];
        int t = qt * 64 + r0 + i;
        float* dst = Out + ((size_t)b * TT + t) * DD + head * 64 + c0;
        *(float4*)dst = make_float4(o[i][0] * invl, o[i][1] * invl,
                                    o[i][2] * invl, o[i][3] * invl);
    }
}

// ---------------------------------------------------------------------------
// SwiGLU elementwise
// ---------------------------------------------------------------------------
__global__ __launch_bounds__(256) void swiglu_k(const float4* __restrict__ g,
                                                const float4* __restrict__ u,
                                                float4* __restrict__ o, size_t n4) {
    size_t i = (size_t)blockIdx.x * 256 + threadIdx.x;
    if (i >= n4) return;
    float4 gv = g[i], uv = u[i];
    float4 r;
    r.x = gv.x / (1.0f + __expf(-gv.x)) * uv.x;
    r.y = gv.y / (1.0f + __expf(-gv.y)) * uv.y;
    r.z = gv.z / (1.0f + __expf(-gv.z)) * uv.z;
    r.w = gv.w / (1.0f + __expf(-gv.w)) * uv.w;
    o[i] = r;
}

// ---------------------------------------------------------------------------
// Launch
// ---------------------------------------------------------------------------
extern "C" void kernel_launch(void* const* d_in, const int* in_sizes, int n_in,
                              void* d_out, int out_size) {
    const float* x     = (const float*)d_in[0];
    const float* w1    = (const float*)d_in[1];
    const float* wqkv  = (const float*)d_in[2];
    const float* wproj = (const float*)d_in[3];
    const float* w2    = (const float*)d_in[4];
    const float* wgate = (const float*)d_in[5];
    const float* wup   = (const float*)d_in[6];
    const float* wdown = (const float*)d_in[7];

    float* out   = (float*)d_out;
    float* out_x = out;
    float* out_k = out + (size_t)BT * DD;
    float* out_v = out + 2 * (size_t)BT * DD;

    float *h, *q, *attn, *x1, *gate, *up;
    cudaGetSymbolAddress((void**)&h,    g_h);
    cudaGetSymbolAddress((void**)&q,    g_q);
    cudaGetSymbolAddress((void**)&attn, g_attn);
    cudaGetSymbolAddress((void**)&x1,   g_x1);
    cudaGetSymbolAddress((void**)&gate, g_gate);
    cudaGetSymbolAddress((void**)&up,   g_up);

    const size_t n4_ff = (size_t)BT * DFF / 4;

    // 1) h = rmsnorm(x, w1)
    rmsnorm_k<<<BT, 256>>>(x, w1, h);
    // 2) qkv gemm + scatter into q scratch / k,v caches (in d_out)
    gemm_tf32<<<dim3(3 * DD / 128, BT / 128), 256>>>(
        h, wqkv, nullptr, nullptr, BT, 3 * DD, DD, 1, q, out_k, out_v);
    // 3) attention
    attn_k<<<dim3(TT / 64, BB * HH), 256>>>(q, out_k, out_v, attn);
    // 4) x1 = x + attn @ w_proj^T
    gemm_tf32<<<dim3(DD / 128, BT / 128), 256>>>(
        attn, wproj, x, x1, BT, DD, DD, 0, nullptr, nullptr, nullptr);
    // 5) h2 = rmsnorm(x1, w2)
    rmsnorm_k<<<BT, 256>>>(x1, w2, h);
    // 6) gate / up
    gemm_tf32<<<dim3(DFF / 128, BT / 128), 256>>>(
        h, wgate, nullptr, gate, BT, DFF, DD, 0, nullptr, nullptr, nullptr);
    gemm_tf32<<<dim3(DFF / 128, BT / 128), 256>>>(
        h, wup, nullptr, up, BT, DFF, DD, 0, nullptr, nullptr, nullptr);
    // 7) act = silu(gate) * up
    swiglu_k<<<(unsigned)((n4_ff + 255) / 256), 256>>>(
        (const float4*)gate, (const float4*)up, (float4*)gate, n4_ff);
    // 8) out_x = x1 + act @ w_down^T
    gemm_tf32<<<dim3(DD / 128, BT / 128), 256>>>(
        gate, wdown, x1, out_x, BT, DD, DFF, 0, nullptr, nullptr, nullptr);
}

// round 8
// speedup vs baseline: 1.2743x; 1.0288x over previous
#include <cuda_runtime.h>
#include <cstdint>

#define BB 2
#define TT 2048
#define DD 1024
#define HH 16
#define DHD 64
#define BT (BB*TT)      // 4096
#define DFF 4096
#define EPS 1e-6f

// ---------------------------------------------------------------------------
// Scratch (device globals; no allocation allowed)
// ---------------------------------------------------------------------------
__device__ float g_h   [(size_t)BT * DD];
__device__ float g_q   [(size_t)BT * DD];
__device__ float g_attn[(size_t)BT * DD];
__device__ float g_x1  [(size_t)BT * DD];
__device__ float g_gate[(size_t)BT * DFF];
__device__ float g_up  [(size_t)BT * DFF];

// ---------------------------------------------------------------------------
// Helpers
// ---------------------------------------------------------------------------
__device__ __forceinline__ float f2tf32(float f) {
    uint32_t u;
    asm("cvt.rna.tf32.f32 %0, %1;" : "=r"(u) : "f"(f));
    return __uint_as_float(u);
}

__device__ __forceinline__ void mma_tf32(float* c, const uint32_t* a, const uint32_t* b) {
    asm volatile(
        "mma.sync.aligned.m16n8k8.row.col.f32.tf32.tf32.f32 "
        "{%0,%1,%2,%3}, {%4,%5,%6,%7}, {%8,%9}, {%0,%1,%2,%3};\n"
        : "+f"(c[0]), "+f"(c[1]), "+f"(c[2]), "+f"(c[3])
        : "r"(a[0]), "r"(a[1]), "r"(a[2]), "r"(a[3]), "r"(b[0]), "r"(b[1]));
}

// ---------------------------------------------------------------------------
// TF32 tensor-core GEMM NT with fragment-packed shared memory.
// C[M,N] = A[M,K] * B[N,K]^T. Block tile 128x128, BK=16, 8 warps (warp 64x32).
//
// Packed layouts (floats), per stage of BK=16 (2 k-steps of 8):
//   A: [ks(2)][mfrag(8)][lane(32)][slot(4)]  slot = khi*2 + mhi  -> {a0,a1,a2,a3}
//   B: [ks(2)][pair(8) ][lane(32)][slot(4)]  slot = plo*2 + khi  -> {e.b0,e.b1,o.b0,o.b1}
// Each mma thread reads its A fragment as ONE float4; one float4 of B feeds
// two n-fragments. Loads are conflict-free; stores are 2-way.
//
// mode 0: plain C (+ optional residual R)
// mode 1: QKV epilogue -> scatter into qp [B,H,T,Dh] / kp / vp caches
// mode 2: A-operand is silu(A)*A2 computed on the fly (fused SwiGLU)
// ---------------------------------------------------------------------------
__global__ __launch_bounds__(256, 2) void gemm_tc(
    const float* __restrict__ A, const float* __restrict__ A2,
    const float* __restrict__ B, const float* __restrict__ R,
    float* __restrict__ C, int M, int N, int K, int mode,
    float* __restrict__ qp, float* __restrict__ kp, float* __restrict__ vp)
{
    __shared__ float As[2][2048];
    __shared__ float Bs[2][2048];

    int t    = threadIdx.x;
    int lane = t & 31, wid = t >> 5;
    int gid  = lane >> 2, tig = lane & 3;
    int bm = blockIdx.y, bn = blockIdx.x;
    int wm = (wid & 1) * 64;
    int wn = (wid >> 1) * 32;
    int mfbase = (wid & 1) * 4;      // first A m-frag of this warp
    int pbase  = (wid >> 1) * 2;     // first B pair of this warp

    // ---- loader mapping: thread covers k = t&15 of rows (t>>4) + 16*i ----
    int kb  = t & 15;                // k within stage
    int mb  = t >> 4;                // base row 0..15
    int ksl = kb >> 3, kkl = kb & 7;
    int tigl = kkl & 3, khil = kkl >> 2;
    // A packed offset: ks*1024 + i*128 + (gid*4+tig)*4 + khi*2 + mhi
    int offA0 = ksl * 1024 + ((mb & 7) * 4 + tigl) * 4 + khil * 2 + ((mb >> 3) & 1);
    // B packed offset: ks*1024 + i*128 + (gid*4+tig)*4 + plo*2 + khi
    int offB0 = ksl * 1024 + ((mb & 7) * 4 + tigl) * 4 + ((mb >> 3) & 1) * 2 + khil;

    const size_t strideAB = (size_t)16 * K;   // 16 rows down
    const float* gA  = A + (size_t)(bm * 128 + mb) * K + kb;
    const float* gA2 = (mode == 2) ? (A2 + (size_t)(bm * 128 + mb) * K + kb) : nullptr;
    const float* gB  = B + (size_t)(bn * 128 + mb) * K + kb;

    float acc[4][4][4];
    #pragma unroll
    for (int mi = 0; mi < 4; mi++)
        #pragma unroll
        for (int ni = 0; ni < 4; ni++)
            #pragma unroll
            for (int e = 0; e < 4; e++) acc[mi][ni][e] = 0.0f;

    const int S = K >> 4;   // stages of BK=16
    float ar[8], br[8];

    // prologue: load + store stage 0
    #pragma unroll
    for (int i = 0; i < 8; i++) {
        float a = gA[i * strideAB];
        if (mode == 2) {
            float u = gA2[i * strideAB];
            a = a / (1.0f + __expf(-a)) * u;
        }
        ar[i] = a;
        br[i] = gB[i * strideAB];
    }
    #pragma unroll
    for (int i = 0; i < 8; i++) {
        As[0][offA0 + i * 128] = f2tf32(ar[i]);
        Bs[0][offB0 + i * 128] = f2tf32(br[i]);
    }
    __syncthreads();

    for (int s = 0; s < S; s++) {
        int buf = s & 1;
        bool more = (s + 1 < S);
        if (more) {
            size_t koff = (size_t)(s + 1) * 16;
            #pragma unroll
            for (int i = 0; i < 8; i++) {
                float a = gA[koff + i * strideAB];
                if (mode == 2) {
                    float u = gA2[koff + i * strideAB];
                    a = a / (1.0f + __expf(-a)) * u;
                }
                ar[i] = a;
                br[i] = gB[koff + i * strideAB];
            }
        }

        // compute: 2 k-steps
        #pragma unroll
        for (int ks = 0; ks < 2; ks++) {
            const float* as = &As[buf][ks * 1024];
            const float* bs = &Bs[buf][ks * 1024];
            float4 af[4], bq[2];
            #pragma unroll
            for (int mi = 0; mi < 4; mi++)
                af[mi] = *(const float4*)&as[((mfbase + mi) * 32 + lane) * 4];
            #pragma unroll
            for (int j = 0; j < 2; j++)
                bq[j] = *(const float4*)&bs[((pbase + j) * 32 + lane) * 4];
            #pragma unroll
            for (int ni = 0; ni < 4; ni++) {
                int j = ni >> 1, half = ni & 1;
                uint32_t b2[2];
                b2[0] = __float_as_uint(half ? bq[j].z : bq[j].x);
                b2[1] = __float_as_uint(half ? bq[j].w : bq[j].y);
                #pragma unroll
                for (int mi = 0; mi < 4; mi++)
                    mma_tf32(acc[mi][ni], (const uint32_t*)&af[mi], b2);
            }
        }

        if (more) {
            int nb = buf ^ 1;
            #pragma unroll
            for (int i = 0; i < 8; i++) {
                As[nb][offA0 + i * 128] = f2tf32(ar[i]);
                Bs[nb][offB0 + i * 128] = f2tf32(br[i]);
            }
            __syncthreads();
        }
    }

    // ---- epilogue ----
    #pragma unroll
    for (int mi = 0; mi < 4; mi++) {
        #pragma unroll
        for (int ni = 0; ni < 4; ni++) {
            int r0 = bm * 128 + wm + mi * 16 + gid;
            int c0 = bn * 128 + wn + ni * 8 + 2 * tig;
            float2 v0 = make_float2(acc[mi][ni][0], acc[mi][ni][1]);
            float2 v1 = make_float2(acc[mi][ni][2], acc[mi][ni][3]);
            if (mode != 1) {
                size_t off0 = (size_t)r0 * N + c0;
                size_t off1 = off0 + (size_t)8 * N;
                if (R) {
                    float2 a0 = *(const float2*)(R + off0);
                    float2 a1 = *(const float2*)(R + off1);
                    v0.x += a0.x; v0.y += a0.y;
                    v1.x += a1.x; v1.y += a1.y;
                }
                *(float2*)(C + off0) = v0;
                *(float2*)(C + off1) = v1;
            } else {
                int which = c0 >> 10;
                int head  = (c0 >> 6) & 15;
                int dh    = c0 & 63;
                float* p = (which == 0) ? qp : (which == 1) ? kp : vp;
                #pragma unroll
                for (int half = 0; half < 2; half++) {
                    int m = r0 + half * 8;
                    int b = m >> 11, tt = m & 2047;
                    size_t dst = (((size_t)(b * HH + head)) * TT + tt) * DHD + dh;
                    *(float2*)(p + dst) = half ? v1 : v0;
                }
            }
        }
    }
}

// ---------------------------------------------------------------------------
// RMSNorm
// ---------------------------------------------------------------------------
__global__ __launch_bounds__(256) void rmsnorm_k(const float* __restrict__ x,
                                                 const float* __restrict__ w,
                                                 float* __restrict__ o) {
    int row = blockIdx.x;
    int tid = threadIdx.x;
    const float4* xr = (const float4*)(x + (size_t)row * DD);
    float4 xv = xr[tid];
    float ss = xv.x * xv.x + xv.y * xv.y + xv.z * xv.z + xv.w * xv.w;
    #pragma unroll
    for (int off = 16; off; off >>= 1) ss += __shfl_xor_sync(0xffffffffu, ss, off);
    __shared__ float sred[8];
    if ((tid & 31) == 0) sred[tid >> 5] = ss;
    __syncthreads();
    if (tid < 8) {
        float v = sred[tid];
        #pragma unroll
        for (int off = 4; off; off >>= 1) v += __shfl_xor_sync(0xffu, v, off);
        if (tid == 0) sred[0] = v;
    }
    __syncthreads();
    float inv = rsqrtf(sred[0] * (1.0f / DD) + EPS);
    float4 wv = ((const float4*)w)[tid];
    ((float4*)(o + (size_t)row * DD))[tid] =
        make_float4(xv.x * inv * wv.x, xv.y * inv * wv.y,
                    xv.z * inv * wv.z, xv.w * inv * wv.w);
}

// ---------------------------------------------------------------------------
// Flash attention (prefill, causal)
// ---------------------------------------------------------------------------
__global__ __launch_bounds__(256) void attn_k(const float* __restrict__ Q,
                                              const float* __restrict__ Kc,
                                              const float* __restrict__ Vc,
                                              float* __restrict__ Out) {
    __shared__ float qs[64 * 64];
    __shared__ float ks[64 * 64];
    __shared__ float vs[64 * 64];

    int qt = blockIdx.x;
    int bh = blockIdx.y;
    int tid = threadIdx.x;
    int tx = tid & 15, ty = tid >> 4;
    int c0 = 4 * tx;
    int r0 = 4 * ty;

    const float* qb = Q + ((size_t)bh * TT + qt * 64) * DHD;
    #pragma unroll
    for (int it = 0; it < 4; it++) {
        int e = it * 256 + tid;
        int r = e >> 4, c4 = (e & 15) * 4;
        float4 v = *(const float4*)(qb + r * 64 + c4);
        v.x *= 0.125f; v.y *= 0.125f; v.z *= 0.125f; v.w *= 0.125f;
        *(float4*)&qs[r * 64 + c4] = v;
    }

    float m[4], l[4], o[4][4];
    #pragma unroll
    for (int i = 0; i < 4; i++) {
        m[i] = -1e30f; l[i] = 0.0f;
        #pragma unroll
        for (int jj = 0; jj < 4; jj++) o[i][jj] = 0.0f;
    }

    int ntiles = qt + 1;
    for (int j = 0; j < ntiles; j++) {
        __syncthreads();
        const float* kb = Kc + ((size_t)bh * TT + j * 64) * DHD;
        const float* vb = Vc + ((size_t)bh * TT + j * 64) * DHD;
        #pragma unroll
        for (int it = 0; it < 4; it++) {
            int e = it * 256 + tid;
            int r = e >> 4, c4 = (e & 15) * 4;
            int g = r + (r >> 1);
            float4 kv = *(const float4*)(kb + r * 64 + c4);
            ks[r * 64 + ((c4 + 0 + g) & 63)] = kv.x;
            ks[r * 64 + ((c4 + 1 + g) & 63)] = kv.y;
            ks[r * 64 + ((c4 + 2 + g) & 63)] = kv.z;
            ks[r * 64 + ((c4 + 3 + g) & 63)] = kv.w;
            float4 vv = *(const float4*)(vb + r * 64 + c4);
            *(float4*)&vs[r * 64 + c4] = vv;
        }
        __syncthreads();

        float s[4][4];
        #pragma unroll
        for (int i = 0; i < 4; i++)
            #pragma unroll
            for (int jj = 0; jj < 4; jj++) s[i][jj] = 0.0f;

        int gc[4];
        #pragma unroll
        for (int jj = 0; jj < 4; jj++) { int c = c0 + jj; gc[jj] = c + (c >> 1); }
        #pragma unroll 8
        for (int k = 0; k < 64; k++) {
            float qv[4], kv[4];
            #pragma unroll
            for (int i = 0; i < 4; i++) qv[i] = qs[(r0 + i) * 64 + k];
            #pragma unroll
            for (int jj = 0; jj < 4; jj++)
                kv[jj] = ks[(c0 + jj) * 64 + ((k + gc[jj]) & 63)];
            #pragma unroll
            for (int i = 0; i < 4; i++)
                #pragma unroll
                for (int jj = 0; jj < 4; jj++)
                    s[i][jj] += qv[i] * kv[jj];
        }

        if (j == qt) {
            #pragma unroll
            for (int i = 0; i < 4; i++) {
                int qrow = qt * 64 + r0 + i;
                #pragma unroll
                for (int jj = 0; jj < 4; jj++) {
                    int key = j * 64 + c0 + jj;
                    if (key > qrow) s[i][jj] = -1e30f;
                }
            }
        }

        #pragma unroll
        for (int i = 0; i < 4; i++) {
            float rm = fmaxf(fmaxf(s[i][0], s[i][1]), fmaxf(s[i][2], s[i][3]));
            #pragma unroll
            for (int off = 1; off < 16; off <<= 1)
                rm = fmaxf(rm, __shfl_xor_sync(0xffffffffu, rm, off));
            float nm = fmaxf(m[i], rm);
            float corr = __expf(m[i] - nm);
            float rs = 0.0f;
            #pragma unroll
            for (int jj = 0; jj < 4; jj++) {
                s[i][jj] = __expf(s[i][jj] - nm);
                rs += s[i][jj];
            }
            #pragma unroll
            for (int off = 1; off < 16; off <<= 1)
                rs += __shfl_xor_sync(0xffffffffu, rs, off);
            l[i] = l[i] * corr + rs;
            m[i] = nm;
            #pragma unroll
            for (int jj = 0; jj < 4; jj++) o[i][jj] *= corr;
        }

        __syncthreads();
        #pragma unroll
        for (int i = 0; i < 4; i++) {
            int r = r0 + i;
            int g = r + (r >> 1);
            #pragma unroll
            for (int jj = 0; jj < 4; jj++)
                ks[r * 64 + ((c0 + jj + g) & 63)] = s[i][jj];
        }
        __syncthreads();

        int gr[4];
        #pragma unroll
        for (int i = 0; i < 4; i++) { int r = r0 + i; gr[i] = r + (r >> 1); }
        #pragma unroll 8
        for (int k = 0; k < 64; k++) {
            float pv[4];
            #pragma unroll
            for (int i = 0; i < 4; i++)
                pv[i] = ks[(r0 + i) * 64 + ((k + gr[i]) & 63)];
            float4 vv = *(const float4*)&vs[k * 64 + c0];
            #pragma unroll
            for (int i = 0; i < 4; i++) {
                o[i][0] += pv[i] * vv.x;
                o[i][1] += pv[i] * vv.y;
                o[i][2] += pv[i] * vv.z;
                o[i][3] += pv[i] * vv.w;
            }
        }
    }

    int b = bh >> 4, head = bh & 15;
    #pragma unroll
    for (int i = 0; i < 4; i++) {
        float invl = 1.0f / l[i];
        int t = qt * 64 + r0 + i;
        float* dst = Out + ((size_t)b * TT + t) * DD + head * 64 + c0;
        *(float4*)dst = make_float4(o[i][0] * invl, o[i][1] * invl,
                                    o[i][2] * invl, o[i][3] * invl);
    }
}

// ---------------------------------------------------------------------------
// Launch
// ---------------------------------------------------------------------------
extern "C" void kernel_launch(void* const* d_in, const int* in_sizes, int n_in,
                              void* d_out, int out_size) {
    const float* x     = (const float*)d_in[0];
    const float* w1    = (const float*)d_in[1];
    const float* wqkv  = (const float*)d_in[2];
    const float* wproj = (const float*)d_in[3];
    const float* w2    = (const float*)d_in[4];
    const float* wgate = (const float*)d_in[5];
    const float* wup   = (const float*)d_in[6];
    const float* wdown = (const float*)d_in[7];

    float* out   = (float*)d_out;
    float* out_x = out;
    float* out_k = out + (size_t)BT * DD;
    float* out_v = out + 2 * (size_t)BT * DD;

    float *h, *q, *attn, *x1, *gate, *up;
    cudaGetSymbolAddress((void**)&h,    g_h);
    cudaGetSymbolAddress((void**)&q,    g_q);
    cudaGetSymbolAddress((void**)&attn, g_attn);
    cudaGetSymbolAddress((void**)&x1,   g_x1);
    cudaGetSymbolAddress((void**)&gate, g_gate);
    cudaGetSymbolAddress((void**)&up,   g_up);

    // 1) h = rmsnorm(x, w1)
    rmsnorm_k<<<BT, 256>>>(x, w1, h);
    // 2) qkv gemm + scatter into q scratch / k,v caches (in d_out)
    gemm_tc<<<dim3(3 * DD / 128, BT / 128), 256>>>(
        h, nullptr, wqkv, nullptr, nullptr, BT, 3 * DD, DD, 1, q, out_k, out_v);
    // 3) attention
    attn_k<<<dim3(TT / 64, BB * HH), 256>>>(q, out_k, out_v, attn);
    // 4) x1 = x + attn @ w_proj^T
    gemm_tc<<<dim3(DD / 128, BT / 128), 256>>>(
        attn, nullptr, wproj, x, x1, BT, DD, DD, 0, nullptr, nullptr, nullptr);
    // 5) h2 = rmsnorm(x1, w2)
    rmsnorm_k<<<BT, 256>>>(x1, w2, h);
    // 6) gate / up
    gemm_tc<<<dim3(DFF / 128, BT / 128), 256>>>(
        h, nullptr, wgate, nullptr, gate, BT, DFF, DD, 0, nullptr, nullptr, nullptr);
    gemm_tc<<<dim3(DFF / 128, BT / 128), 256>>>(
        h, nullptr, wup, nullptr, up, BT, DFF, DD, 0, nullptr, nullptr, nullptr);
    // 7) out_x = x1 + (silu(gate)*up) @ w_down^T   (SwiGLU fused into A-load)
    gemm_tc<<<dim3(DD / 128, BT / 128), 256>>>(
        gate, up, wdown, x1, out_x, BT, DD, DFF, 2, nullptr, nullptr, nullptr);
}